// round 1
// baseline (speedup 1.0000x reference)
#include <cuda_runtime.h>
#include <cstdint>

#define NROWS 8192
#define DIM   128
#define BM    128
#define BN    128
#define NTILES (NROWS / BN)          // 64
#define JSPLIT 2
#define TILES_PER (NTILES / JSPLIT)  // 32
#define MARGIN_F 0.3f

// Scratch (device globals; no allocations allowed)
__device__ unsigned int g_ap2[NROWS];   // max same-label d^2 (float bits)
__device__ unsigned int g_an2[NROWS];   // min diff-label d^2 (float bits)
__device__ float        g_sq[NROWS];    // ||x_i||^2
__device__ int          g_lab[NROWS];   // normalized labels (int32)

// ---------------------------------------------------------------------------
// Label prep: targets may be int64 (reference declares int64) or int32 (JAX
// x64-disabled demotion). Values are in [0, 512). If int64 little-endian, the
// int32 view is [v0,0,v1,0,...]; detect "all odd words zero" over the first
// 4096 rows (in-bounds for both interpretations) and normalize.
// ---------------------------------------------------------------------------
__global__ void prep_labels_kernel(const int* __restrict__ t32) {
    __shared__ int s_all64;
    if (threadIdx.x == 0) s_all64 = 1;
    __syncthreads();
    int local = 1;
    for (int i = threadIdx.x; i < 4096; i += 256)
        if (t32[2 * i + 1] != 0) local = 0;
    if (!local) atomicAnd(&s_all64, 0);
    __syncthreads();
    const bool is64 = (s_all64 != 0);
    for (int i = threadIdx.x; i < NROWS; i += 256)
        g_lab[i] = is64 ? t32[2 * i] : t32[i];
}

// ---------------------------------------------------------------------------
// Row squared norms: one warp per row, coalesced float4 loads. Also warms L2
// with the full 4 MB input so the main kernel's gathers hit L2.
// ---------------------------------------------------------------------------
__global__ void sq_kernel(const float* __restrict__ x) {
    int gwarp = (blockIdx.x * blockDim.x + threadIdx.x) >> 5;
    int lane  = threadIdx.x & 31;
    if (gwarp >= NROWS) return;
    float4 v = reinterpret_cast<const float4*>(x + (size_t)gwarp * DIM)[lane];
    float s = v.x * v.x + v.y * v.y + v.z * v.z + v.w * v.w;
#pragma unroll
    for (int o = 16; o; o >>= 1) s += __shfl_xor_sync(0xffffffffu, s, o);
    if (lane == 0) g_sq[gwarp] = s;
}

__global__ void init_kernel() {
    int i = blockIdx.x * blockDim.x + threadIdx.x;
    if (i < NROWS) { g_ap2[i] = 0u; g_an2[i] = 0x7f800000u; }  // 0 / +inf
}

// ---------------------------------------------------------------------------
// Transposing tile loader: global row-major [rows][128] -> smem float4 array
// dst[k*32 + (f ^ (k&31))], where chunk f holds rows 4f..4f+3 at column k.
//  - Global: per warp, lanes span 32 consecutive k at fixed row -> 128B coalesced.
//  - STS: chunk = f ^ lane-permutation -> conflict-free per 8-lane phase.
// ---------------------------------------------------------------------------
__device__ __forceinline__ void load_tile_T(float4* __restrict__ dst,
                                            const float* __restrict__ x,
                                            int rowbase, int tid) {
#pragma unroll
    for (int i = 0; i < 16; i++) {
        int idx = tid + i * 256;     // 0..4095
        int f   = idx >> 7;          // 0..31  (row-quad)
        int k   = idx & 127;         // 0..127 (column)
        const float* p = x + (size_t)(rowbase + f * 4) * DIM + k;
        float4 v = make_float4(p[0], p[DIM], p[2 * DIM], p[3 * DIM]);
        dst[k * 32 + (f ^ (k & 31))] = v;
    }
}

// ---------------------------------------------------------------------------
// Main fused kernel: 128x128 block tile, 8x8 per thread, full K=128.
// grid = (64, JSPLIT). Per-row running max(d^2, same-label) / min(d^2, diff).
// ---------------------------------------------------------------------------
__global__ void __launch_bounds__(256, 1)
triplet_main_kernel(const float* __restrict__ x) {
    extern __shared__ float4 smem[];
    float4* A4   = smem;                 // 4096 float4 (64 KB)
    float4* B4   = smem + 4096;          // 2 x 4096 float4 (128 KB)
    float*  sqj  = (float*)(smem + 4096 + 8192);  // [2][128]
    int*    labj = (int*)(sqj + 2 * BN);          // [2][128]

    const int tid = threadIdx.x;
    const int tx  = tid & 15;
    const int ty  = tid >> 4;
    const int ibase = blockIdx.x * BM;
    const int t0    = blockIdx.y * TILES_PER;

    load_tile_T(A4, x, ibase, tid);
    load_tile_T(B4, x, t0 * BN, tid);
    if (tid < BN) {
        sqj[tid]  = g_sq[t0 * BN + tid];
        labj[tid] = g_lab[t0 * BN + tid];
    }

    float sqi[8]; int labi[8];
    float ap[8], an[8];
#pragma unroll
    for (int r = 0; r < 8; r++) {
        int row = ibase + ((r < 4) ? ty * 4 + r : 64 + ty * 4 + (r - 4));
        sqi[r]  = g_sq[row];
        labi[r] = g_lab[row];
        ap[r] = 0.0f;
        an[r] = __int_as_float(0x7f800000);
    }
    __syncthreads();

    for (int t = t0; t < t0 + TILES_PER; ++t) {
        const int buf = (t - t0) & 1;

        // Prefetch next B tile into the other buffer (overlaps with compute).
        if (t + 1 < t0 + TILES_PER) {
            const int nb = buf ^ 1;
            const int jb = (t + 1) * BN;
            load_tile_T(B4 + nb * 4096, x, jb, tid);
            if (tid < BN) {
                sqj[nb * BN + tid]  = g_sq[jb + tid];
                labj[nb * BN + tid] = g_lab[jb + tid];
            }
        }

        const float4* Bb = B4 + buf * 4096;
        float acc[8][8];
#pragma unroll
        for (int r = 0; r < 8; r++)
#pragma unroll
            for (int c = 0; c < 8; c++) acc[r][c] = 0.0f;

#pragma unroll 4
        for (int k = 0; k < DIM; ++k) {
            const int cx = k & 31;
            float4 A0 = A4[k * 32 + (ty ^ cx)];
            float4 A1 = A4[k * 32 + ((16 + ty) ^ cx)];
            float4 B0 = Bb[k * 32 + (tx ^ cx)];
            float4 B1 = Bb[k * 32 + ((16 + tx) ^ cx)];
            float a[8] = {A0.x, A0.y, A0.z, A0.w, A1.x, A1.y, A1.z, A1.w};
            float b[8] = {B0.x, B0.y, B0.z, B0.w, B1.x, B1.y, B1.z, B1.w};
#pragma unroll
            for (int r = 0; r < 8; r++)
#pragma unroll
                for (int c = 0; c < 8; c++)
                    acc[r][c] = fmaf(a[r], b[c], acc[r][c]);
        }

        // Epilogue: d^2 = sqi + sqj - 2*dot, clamp, mine on d^2 (sqrt deferred)
        float sjv[8]; int ljv[8];
#pragma unroll
        for (int c = 0; c < 8; c++) {
            int col = (c < 4) ? tx * 4 + c : 64 + tx * 4 + (c - 4);
            sjv[c] = sqj[buf * BN + col];
            ljv[c] = labj[buf * BN + col];
        }
#pragma unroll
        for (int r = 0; r < 8; r++) {
#pragma unroll
            for (int c = 0; c < 8; c++) {
                float d2 = fmaf(-2.0f, acc[r][c], sqi[r] + sjv[c]);
                d2 = fmaxf(d2, 1e-12f);
                if (labi[r] == ljv[c]) ap[r] = fmaxf(ap[r], d2);
                else                   an[r] = fminf(an[r], d2);
            }
        }
        __syncthreads();
    }

    // Reduce across the 16 tx-lanes (lanes l and l^8.. stay in 16-lane group)
#pragma unroll
    for (int o = 8; o; o >>= 1) {
#pragma unroll
        for (int r = 0; r < 8; r++) {
            ap[r] = fmaxf(ap[r], __shfl_xor_sync(0xffffffffu, ap[r], o));
            an[r] = fminf(an[r], __shfl_xor_sync(0xffffffffu, an[r], o));
        }
    }
    if (tx == 0) {
#pragma unroll
        for (int r = 0; r < 8; r++) {
            int row = ibase + ((r < 4) ? ty * 4 + r : 64 + ty * 4 + (r - 4));
            atomicMax(&g_ap2[row], __float_as_uint(ap[r]));  // all values > 0
            atomicMin(&g_an2[row], __float_as_uint(an[r]));
        }
    }
}

// ---------------------------------------------------------------------------
// Finalize: sqrt the mined d^2, margin ranking loss + precision means.
// ---------------------------------------------------------------------------
__global__ void finalize_kernel(float* __restrict__ out, int out_size) {
    __shared__ float sl[256], sp[256];
    float loss = 0.0f, prec = 0.0f;
    for (int i = threadIdx.x; i < NROWS; i += 256) {
        float dap = sqrtf(__uint_as_float(g_ap2[i]));
        float dan = sqrtf(__uint_as_float(g_an2[i]));
        loss += fmaxf(0.0f, MARGIN_F - (dan - dap));
        prec += (dan > dap) ? 1.0f : 0.0f;
    }
    sl[threadIdx.x] = loss;
    sp[threadIdx.x] = prec;
    __syncthreads();
#pragma unroll
    for (int s = 128; s > 0; s >>= 1) {
        if (threadIdx.x < s) {
            sl[threadIdx.x] += sl[threadIdx.x + s];
            sp[threadIdx.x] += sp[threadIdx.x + s];
        }
        __syncthreads();
    }
    if (threadIdx.x == 0) {
        out[0] = sl[0] / (float)NROWS;
        if (out_size > 1) out[1] = sp[0] / (float)NROWS;
    }
}

// ---------------------------------------------------------------------------
extern "C" void kernel_launch(void* const* d_in, const int* in_sizes, int n_in,
                              void* d_out, int out_size) {
    const float* x   = (const float*)d_in[0];
    const int*   t32 = (const int*)d_in[1];  // raw view; prep normalizes dtype
    (void)in_sizes; (void)n_in;

    const int smem_bytes = (4096 + 8192) * 16 + 2 * BN * 4 + 2 * BN * 4;
    cudaFuncSetAttribute(triplet_main_kernel,
                         cudaFuncAttributeMaxDynamicSharedMemorySize, smem_bytes);

    prep_labels_kernel<<<1, 256>>>(t32);
    sq_kernel<<<NROWS * 32 / 256, 256>>>(x);
    init_kernel<<<NROWS / 256, 256>>>();
    triplet_main_kernel<<<dim3(NROWS / BM, JSPLIT), 256, smem_bytes>>>(x);
    finalize_kernel<<<1, 256>>>((float*)d_out, out_size);
}